// round 4
// baseline (speedup 1.0000x reference)
#include <cuda_runtime.h>
#include <math.h>

#define LL 512
#define CS 384
#define CZ 256
#define PW 1152
#define SH 3648
#define WLL 0.57735026918962576f
#define WCC 0.23570226039551584f

__device__ float g_Wcat[CS * PW];
__device__ float g_proj[LL * PW];   // [q 0|k 192|v 384|qp 576|kp 720|vp 864]
__device__ float g_R[LL * 9];
__device__ float g_t[LL * 3];
__device__ float g_coef[12];
__device__ float g_qpp[LL * 144];       // row-major (per-i use)
__device__ float g_kT[192 * LL];        // j-contiguous
__device__ float g_vT[192 * LL];        // j-contiguous
__device__ float g_kppT[144 * LL];      // j-contiguous
__device__ float g_vppT[288 * LL];      // j-contiguous
__device__ float g_B[LL * LL * 12];     // bias logits [i*512+j][12]
__device__ float g_shid[LL * SH];
__device__ float g_parts[4 * LL * CS];
__device__ float g_s1[LL * CS];
__device__ float g_h1[LL * CS];
__device__ float g_h2[LL * CS];

__global__ void pack_prep(const float* __restrict__ Wq, const float* __restrict__ Wk,
                          const float* __restrict__ Wv, const float* __restrict__ Wqp,
                          const float* __restrict__ Wkp, const float* __restrict__ Wvp,
                          const float* __restrict__ quat, const float* __restrict__ trsl,
                          const float* __restrict__ scale)
{
    int idx = blockIdx.x * blockDim.x + threadIdx.x;
    if (idx < CS * PW) {
        int r = idx / PW, c = idx - r * PW;
        float v;
        if      (c < 192)  v = Wq [r*192 + c];
        else if (c < 384)  v = Wk [r*192 + c-192];
        else if (c < 576)  v = Wv [r*192 + c-384];
        else if (c < 720)  v = Wqp[r*144 + c-576];
        else if (c < 864)  v = Wkp[r*144 + c-720];
        else               v = Wvp[r*288 + c-864];
        g_Wcat[idx] = v;
    }
    if (idx < LL) {
        float w = quat[idx*4], x = quat[idx*4+1], y = quat[idx*4+2], z = quat[idx*4+3];
        float inv = rsqrtf(w*w + x*x + y*y + z*z);
        w *= inv; x *= inv; y *= inv; z *= inv;
        float* R = g_R + idx*9;
        R[0]=1.f-2.f*(y*y+z*z); R[1]=2.f*(x*y-w*z);     R[2]=2.f*(x*z+w*y);
        R[3]=2.f*(x*y+w*z);     R[4]=1.f-2.f*(x*x+z*z); R[5]=2.f*(y*z-w*x);
        R[6]=2.f*(x*z-w*y);     R[7]=2.f*(y*z+w*x);     R[8]=1.f-2.f*(x*x+y*y);
        g_t[idx*3]=trsl[idx*3]; g_t[idx*3+1]=trsl[idx*3+1]; g_t[idx*3+2]=trsl[idx*3+2];
    }
    if (idx < 12) g_coef[idx] = 0.5f * WCC * log1pf(expf(scale[idx]));
}

// per-i: transform points (write transposed kpp/vpp), transpose k/v
__global__ void transform()
{
    int i = blockIdx.x, pt = threadIdx.x;   // 384 threads
    if (pt < 192) g_kT[pt * LL + i] = g_proj[(size_t)i*PW + 192 + pt];
    else          g_vT[(pt-192) * LL + i] = g_proj[(size_t)i*PW + 384 + (pt-192)];
    if (pt >= 192) return;
    const float* R = g_R + i*9;
    const float* t = g_t + i*3;
    const float* src;
    if (pt < 48)      src = g_proj + (size_t)i*PW + 576 + pt*3;
    else if (pt < 96) src = g_proj + (size_t)i*PW + 720 + (pt-48)*3;
    else              src = g_proj + (size_t)i*PW + 864 + (pt-96)*3;
    float px = src[0], py = src[1], pz = src[2];
    float ox = R[0]*px + R[1]*py + R[2]*pz + t[0];
    float oy = R[3]*px + R[4]*py + R[5]*pz + t[1];
    float oz = R[6]*px + R[7]*py + R[8]*pz + t[2];
    if (pt < 48) {
        float* d = g_qpp + i*144 + pt*3;
        d[0] = ox; d[1] = oy; d[2] = oz;
    } else if (pt < 96) {
        int p = pt - 48;
        g_kppT[(p*3+0)*LL + i] = ox;
        g_kppT[(p*3+1)*LL + i] = oy;
        g_kppT[(p*3+2)*LL + i] = oz;
    } else {
        int p = pt - 96;
        g_vppT[(p*3+0)*LL + i] = ox;
        g_vppT[(p*3+1)*LL + i] = oy;
        g_vppT[(p*3+2)*LL + i] = oz;
    }
}

// bias GEMM: B[262144, 12] = z[262144, 256] @ Wb[256, 12]
// CTA = 256 rows; 256 threads = (q = tid&63 -> rows q+64r, hp = tid>>6 -> 3 heads)
__global__ __launch_bounds__(256) void bias_gemm(const float* __restrict__ z,
                                                 const float* __restrict__ Wb)
{
    __shared__ float sWb[CZ * 12];      // 12 KB
    __shared__ float sAz[256][33];      // 33.8 KB, pad 33 -> conflict-free
    int row0 = blockIdx.x * 256;
    int tid = threadIdx.x;
    int q = tid & 63, hp = tid >> 6;

    for (int x = tid; x < CZ*12; x += 256) sWb[x] = Wb[x];

    float acc[4][3] = {};
    for (int ch = 0; ch < 8; ch++) {            // 8 chunks of 32 columns
        __syncthreads();
        // stage 256 rows x 32 cols, coalesced
        #pragma unroll
        for (int t = 0; t < 8; t++) {
            int idx = tid + t * 256;            // 2048 float4
            int row = idx >> 3, c4 = idx & 7;
            float4 v = *(const float4*)(z + (size_t)(row0 + row) * CZ + ch*32 + c4*4);
            sAz[row][c4*4+0] = v.x; sAz[row][c4*4+1] = v.y;
            sAz[row][c4*4+2] = v.z; sAz[row][c4*4+3] = v.w;
        }
        __syncthreads();
        #pragma unroll 8
        for (int c = 0; c < 32; c++) {
            float w0 = sWb[(ch*32+c)*12 + hp*3 + 0];
            float w1 = sWb[(ch*32+c)*12 + hp*3 + 1];
            float w2 = sWb[(ch*32+c)*12 + hp*3 + 2];
            #pragma unroll
            for (int r = 0; r < 4; r++) {
                float a = sAz[q + 64*r][c];
                acc[r][0] = fmaf(a, w0, acc[r][0]);
                acc[r][1] = fmaf(a, w1, acc[r][1]);
                acc[r][2] = fmaf(a, w2, acc[r][2]);
            }
        }
    }
    #pragma unroll
    for (int r = 0; r < 4; r++) {
        float* o = g_B + (size_t)(row0 + q + 64*r) * 12 + hp*3;
        o[0] = acc[r][0]; o[1] = acc[r][1]; o[2] = acc[r][2];
    }
}

// 64x64 tile SGEMM, 256 threads, 4x4 per thread, split-K along gridDim.z
__global__ __launch_bounds__(256) void gemm64(const float* __restrict__ A,
                                              const float* __restrict__ B,
                                              float* __restrict__ C,
                                              int lda, int ldb, int ldc,
                                              int kSlice, int K, int partStride)
{
    __shared__ float As[16][64];
    __shared__ float Bs[16][64];
    int n0 = blockIdx.x * 64, m0 = blockIdx.y * 64;
    int k0 = blockIdx.z * kSlice;
    int kend = min(K, k0 + kSlice);
    float* Cc = C + (size_t)blockIdx.z * partStride;
    int tid = threadIdx.x;
    int tx = tid & 15, ty = tid >> 4;
    int ar = tid >> 2, ac = (tid & 3) << 2;
    float acc[4][4] = {};
    for (int kt = k0; kt < kend; kt += 16) {
        float4 av = *(const float4*)(A + (size_t)(m0 + ar) * lda + kt + ac);
        As[ac+0][ar] = av.x; As[ac+1][ar] = av.y; As[ac+2][ar] = av.z; As[ac+3][ar] = av.w;
        *(float4*)&Bs[ty][tx << 2] = *(const float4*)(B + (size_t)(kt + ty) * ldb + n0 + (tx << 2));
        __syncthreads();
        #pragma unroll
        for (int kk = 0; kk < 16; kk++) {
            float4 a = *(float4*)&As[kk][ty << 2];
            float4 b = *(float4*)&Bs[kk][tx << 2];
            acc[0][0]=fmaf(a.x,b.x,acc[0][0]); acc[0][1]=fmaf(a.x,b.y,acc[0][1]);
            acc[0][2]=fmaf(a.x,b.z,acc[0][2]); acc[0][3]=fmaf(a.x,b.w,acc[0][3]);
            acc[1][0]=fmaf(a.y,b.x,acc[1][0]); acc[1][1]=fmaf(a.y,b.y,acc[1][1]);
            acc[1][2]=fmaf(a.y,b.z,acc[1][2]); acc[1][3]=fmaf(a.y,b.w,acc[1][3]);
            acc[2][0]=fmaf(a.z,b.x,acc[2][0]); acc[2][1]=fmaf(a.z,b.y,acc[2][1]);
            acc[2][2]=fmaf(a.z,b.z,acc[2][2]); acc[2][3]=fmaf(a.z,b.w,acc[2][3]);
            acc[3][0]=fmaf(a.w,b.x,acc[3][0]); acc[3][1]=fmaf(a.w,b.y,acc[3][1]);
            acc[3][2]=fmaf(a.w,b.z,acc[3][2]); acc[3][3]=fmaf(a.w,b.w,acc[3][3]);
        }
        __syncthreads();
    }
    #pragma unroll
    for (int r = 0; r < 4; r++)
        *(float4*)(Cc + (size_t)(m0 + (ty<<2) + r) * ldc + n0 + (tx<<2)) =
            make_float4(acc[r][0], acc[r][1], acc[r][2], acc[r][3]);
}

__global__ void combine(const float* __restrict__ parts, int nparts, int partStride,
                        const float* __restrict__ bias, float* __restrict__ out,
                        int total, int N)
{
    int idx = blockIdx.x * blockDim.x + threadIdx.x;
    if (idx >= total) return;
    float v = parts[idx];
    for (int p = 1; p < nparts; p++) v += parts[(size_t)p * partStride + idx];
    v += bias[idx % N];
    out[idx] = fmaxf(v, 0.f);
}

__global__ void ln_combine(const float* __restrict__ parts, int nparts, int partStride,
                           const float* __restrict__ bias, const float* __restrict__ resid,
                           const float* __restrict__ gg, const float* __restrict__ bb,
                           float* __restrict__ out)
{
    int i = blockIdx.x, t = threadIdx.x;   // 128 threads
    float v[3];
    #pragma unroll
    for (int k = 0; k < 3; k++) {
        int c = t + k * 128;
        size_t off = (size_t)i * CS + c;
        float x = parts[off];
        for (int p = 1; p < nparts; p++) x += parts[(size_t)p * partStride + off];
        v[k] = x + bias[c] + resid[off];
    }
    float s = v[0]+v[1]+v[2], q = v[0]*v[0]+v[1]*v[1]+v[2]*v[2];
    #pragma unroll
    for (int o = 16; o; o >>= 1) {
        s += __shfl_xor_sync(0xffffffffu, s, o);
        q += __shfl_xor_sync(0xffffffffu, q, o);
    }
    __shared__ float ss[4], sq[4];
    int w = t >> 5, lane = t & 31;
    if (lane == 0) { ss[w] = s; sq[w] = q; }
    __syncthreads();
    if (t == 0) {
        float S = ss[0]+ss[1]+ss[2]+ss[3], Q = sq[0]+sq[1]+sq[2]+sq[3];
        float m = S * (1.f/CS);
        ss[0] = m; sq[0] = rsqrtf(Q*(1.f/CS) - m*m + 1e-5f);
    }
    __syncthreads();
    float m = ss[0], r = sq[0];
    float* o = out + (size_t)i * CS;
    #pragma unroll
    for (int k = 0; k < 3; k++) {
        int c = t + k * 128;
        o[c] = (v[k]-m)*r*gg[c] + bb[c];
    }
}

// fused attention (bias precomputed in g_B): one CTA per query row i
__global__ __launch_bounds__(256) void attn(const float* __restrict__ z)
{
    __shared__ float sA[LL * 12];     // 24 KB
    __shared__ float sq[192], sqpp[144], sR[9], st3[3], scoef[12], sOVP[288];

    int i = blockIdx.x, tid = threadIdx.x;
    int lane = tid & 31, w = tid >> 5;
    const float* zrow = z + (size_t)i * LL * CZ;

    if (tid < 192) sq[tid] = g_proj[(size_t)i * PW + tid];
    if (tid < 144) sqpp[tid] = g_qpp[i*144 + tid];
    if (tid < 9)   sR[tid] = g_R[i*9 + tid];
    if (tid < 3)   st3[tid] = g_t[i*3 + tid];
    if (tid < 12)  scoef[tid] = g_coef[tid];
    __syncthreads();

    // ---- phase 1: logits for rows j=tid and j=tid+256 (kT/kppT coalesced) ----
    #pragma unroll
    for (int jj = 0; jj < 2; jj++) {
        int j = tid + jj * 256;
        const float4* bp = (const float4*)(g_B + ((size_t)i * LL + j) * 12);
        float4 b0 = bp[0], b1 = bp[1], b2 = bp[2];
        float bh[12] = {b0.x,b0.y,b0.z,b0.w, b1.x,b1.y,b1.z,b1.w, b2.x,b2.y,b2.z,b2.w};
        #pragma unroll
        for (int h = 0; h < 12; h++) {
            float qk = 0.f;
            #pragma unroll
            for (int d = 0; d < 16; d++)
                qk = fmaf(sq[h*16+d], g_kT[(h*16+d)*LL + j], qk);
            float d2 = 0.f;
            #pragma unroll
            for (int e = 0; e < 12; e++) {
                float dd = sqpp[h*12+e] - g_kppT[(h*12+e)*LL + j];
                d2 = fmaf(dd, dd, d2);
            }
            sA[j*12 + h] = WLL * (qk * 0.25f + bh[h] - scoef[h] * d2);
        }
    }
    __syncthreads();

    // ---- softmax over j per head ----
    for (int h = w; h < 12; h += 8) {
        float m = -1e30f;
        for (int j = lane; j < LL; j += 32) m = fmaxf(m, sA[j*12+h]);
        #pragma unroll
        for (int o = 16; o; o >>= 1) m = fmaxf(m, __shfl_xor_sync(0xffffffffu, m, o));
        float sum = 0.f;
        for (int j = lane; j < LL; j += 32) {
            float e = __expf(sA[j*12+h] - m);
            sA[j*12+h] = e; sum += e;
        }
        #pragma unroll
        for (int o = 16; o; o >>= 1) sum += __shfl_xor_sync(0xffffffffu, sum, o);
        float inv = 1.f / sum;
        for (int j = lane; j < LL; j += 32) sA[j*12+h] *= inv;
    }
    __syncthreads();

    // ---- op = a^T @ z : 4 head-triples x 64 col-quads ----
    {
        int h0 = (tid >> 6) * 3;
        int cc = (tid & 63) << 2;
        float acc[3][4] = {};
        #pragma unroll 4
        for (int j = 0; j < LL; j++) {
            float4 zv = *(const float4*)(zrow + (size_t)j * CZ + cc);
            float a0 = sA[j*12+h0], a1 = sA[j*12+h0+1], a2 = sA[j*12+h0+2];
            acc[0][0]=fmaf(a0,zv.x,acc[0][0]); acc[0][1]=fmaf(a0,zv.y,acc[0][1]);
            acc[0][2]=fmaf(a0,zv.z,acc[0][2]); acc[0][3]=fmaf(a0,zv.w,acc[0][3]);
            acc[1][0]=fmaf(a1,zv.x,acc[1][0]); acc[1][1]=fmaf(a1,zv.y,acc[1][1]);
            acc[1][2]=fmaf(a1,zv.z,acc[1][2]); acc[1][3]=fmaf(a1,zv.w,acc[1][3]);
            acc[2][0]=fmaf(a2,zv.x,acc[2][0]); acc[2][1]=fmaf(a2,zv.y,acc[2][1]);
            acc[2][2]=fmaf(a2,zv.z,acc[2][2]); acc[2][3]=fmaf(a2,zv.w,acc[2][3]);
        }
        float* orow = g_shid + (size_t)i * SH;
        #pragma unroll
        for (int hh = 0; hh < 3; hh++)
            *(float4*)(orow + (h0+hh)*304 + cc) =
                make_float4(acc[hh][0], acc[hh][1], acc[hh][2], acc[hh][3]);
    }

    // ---- ov (16 dims) + ovp_g (24 dims) per head: j-contiguous streams ----
    if (tid < 240) {
        int h = tid / 20, o = (tid % 20) * 2;
        const float* s0;
        if (o < 16) s0 = g_vT + (h*16+o)*LL;
        else        s0 = g_vppT + (h*24+o-16)*LL;
        const float* s1p = s0 + LL;
        float a0 = 0.f, a1 = 0.f;
        #pragma unroll 4
        for (int j = 0; j < LL; j += 4) {
            float4 v0 = *(const float4*)(s0 + j);
            float4 v1 = *(const float4*)(s1p + j);
            float w0 = sA[(j+0)*12+h], w1 = sA[(j+1)*12+h];
            float w2 = sA[(j+2)*12+h], w3 = sA[(j+3)*12+h];
            a0 = fmaf(w0,v0.x,fmaf(w1,v0.y,fmaf(w2,v0.z,fmaf(w3,v0.w,a0))));
            a1 = fmaf(w0,v1.x,fmaf(w1,v1.y,fmaf(w2,v1.z,fmaf(w3,v1.w,a1))));
        }
        float* orow = g_shid + (size_t)i * SH + h * 304;
        if (o < 16) { orow[256+o] = a0; orow[257+o] = a1; }
        else        { sOVP[h*24 + o-16] = a0; sOVP[h*24 + o-15] = a1; }
    }
    __syncthreads();

    // ---- ovp = R^T (ovp_g - t), plus norms ----
    if (tid < 96) {
        int h = tid >> 3, vv = tid & 7;
        float gx = sOVP[h*24 + vv*3 + 0] - st3[0];
        float gy = sOVP[h*24 + vv*3 + 1] - st3[1];
        float gz = sOVP[h*24 + vv*3 + 2] - st3[2];
        float lx = sR[0]*gx + sR[3]*gy + sR[6]*gz;
        float ly = sR[1]*gx + sR[4]*gy + sR[7]*gz;
        float lz = sR[2]*gx + sR[5]*gy + sR[8]*gz;
        float* orow = g_shid + (size_t)i * SH + h * 304;
        orow[272 + vv*3 + 0] = lx;
        orow[272 + vv*3 + 1] = ly;
        orow[272 + vv*3 + 2] = lz;
        orow[296 + vv] = sqrtf(lx*lx + ly*ly + lz*lz);
    }
}

extern "C" void kernel_launch(void* const* d_in, const int* in_sizes, int n_in,
                              void* d_out, int out_size)
{
    const float* s    = (const float*)d_in[0];
    const float* z    = (const float*)d_in[1];
    const float* quat = (const float*)d_in[2];
    const float* trsl = (const float*)d_in[3];
    const float* Wq   = (const float*)d_in[4];
    const float* Wk   = (const float*)d_in[5];
    const float* Wv   = (const float*)d_in[6];
    const float* Wqp  = (const float*)d_in[7];
    const float* Wkp  = (const float*)d_in[8];
    const float* Wvp  = (const float*)d_in[9];
    const float* Wb   = (const float*)d_in[10];
    const float* Ws   = (const float*)d_in[11];
    const float* bs   = (const float*)d_in[12];
    const float* scale= (const float*)d_in[13];
    const float* g1   = (const float*)d_in[14];
    const float* b1   = (const float*)d_in[15];
    const float* Wm1  = (const float*)d_in[16];
    const float* bm1  = (const float*)d_in[17];
    const float* Wm2  = (const float*)d_in[18];
    const float* bm2  = (const float*)d_in[19];
    const float* Wm3  = (const float*)d_in[20];
    const float* bm3  = (const float*)d_in[21];
    const float* g2   = (const float*)d_in[22];
    const float* b2   = (const float*)d_in[23];
    float* out = (float*)d_out;

    void *pWcat, *pShid, *pParts, *pS1, *pH1, *pH2;
    cudaGetSymbolAddress(&pWcat,  g_Wcat);
    cudaGetSymbolAddress(&pShid,  g_shid);
    cudaGetSymbolAddress(&pParts, g_parts);
    cudaGetSymbolAddress(&pS1,    g_s1);
    cudaGetSymbolAddress(&pH1,    g_h1);
    cudaGetSymbolAddress(&pH2,    g_h2);
    float* Wcat = (float*)pWcat;
    float* shid = (float*)pShid;  float* parts = (float*)pParts;
    float* s1 = (float*)pS1;      float* h1 = (float*)pH1;
    float* h2 = (float*)pH2;
    void* pProj; cudaGetSymbolAddress(&pProj, g_proj);
    float* proj = (float*)pProj;

    const int TOT = LL * CS;

    pack_prep<<<(CS*PW + 255)/256, 256>>>(Wq, Wk, Wv, Wqp, Wkp, Wvp, quat, trsl, scale);
    bias_gemm<<<(LL*LL)/256, 256>>>(z, Wb);
    gemm64<<<dim3(PW/64, LL/64, 1), 256>>>(s, Wcat, proj, CS, PW, PW, CS, CS, 0);
    transform<<<LL, 384>>>();
    attn<<<LL, 256>>>(z);
    gemm64<<<dim3(CS/64, LL/64, 4), 256>>>(shid, Ws, parts, SH, CS, CS, SH/4, SH, TOT);
    ln_combine<<<LL, 128>>>(parts, 4, TOT, bs, s, g1, b1, s1);
    gemm64<<<dim3(CS/64, LL/64, 3), 256>>>(s1, Wm1, parts, CS, CS, CS, CS/3, CS, TOT);
    combine<<<(TOT+255)/256, 256>>>(parts, 3, TOT, bm1, h1, TOT, CS);
    gemm64<<<dim3(CS/64, LL/64, 3), 256>>>(h1, Wm2, parts, CS, CS, CS, CS/3, CS, TOT);
    combine<<<(TOT+255)/256, 256>>>(parts, 3, TOT, bm2, h2, TOT, CS);
    gemm64<<<dim3(CS/64, LL/64, 3), 256>>>(h2, Wm3, parts, CS, CS, CS, CS/3, CS, TOT);
    ln_combine<<<LL, 128>>>(parts, 3, TOT, bm3, s1, g2, b2, out);
}

// round 5
// speedup vs baseline: 1.2305x; 1.2305x over previous
#include <cuda_runtime.h>
#include <math.h>

#define LL 512
#define CS 384
#define CZ 256
#define PW 1152
#define SH 3648
#define WLL 0.57735026918962576f
#define WCC 0.23570226039551584f

__device__ float g_Wcat[CS * PW];
__device__ float g_proj[LL * PW];   // [q 0|k 192|v 384|qp 576|kp 720|vp 864]
__device__ float g_R[LL * 9];
__device__ float g_t[LL * 3];
__device__ float g_coef[12];
__device__ float g_qpp[LL * 144];       // row-major (per-i use)
__device__ float g_kT[192 * LL];        // j-contiguous
__device__ float g_vT[192 * LL];        // j-contiguous
__device__ float g_kppT[144 * LL];      // j-contiguous
__device__ float g_vppT[288 * LL];      // j-contiguous
__device__ float g_Bt[12 * LL * LL];    // bias logits, head-major [h][i*512+j]
__device__ float g_shid[LL * SH];
__device__ float g_parts[4 * LL * CS];
__device__ float g_s1[LL * CS];
__device__ float g_h1[LL * CS];
__device__ float g_h2[LL * CS];

__global__ void pack_prep(const float* __restrict__ Wq, const float* __restrict__ Wk,
                          const float* __restrict__ Wv, const float* __restrict__ Wqp,
                          const float* __restrict__ Wkp, const float* __restrict__ Wvp,
                          const float* __restrict__ quat, const float* __restrict__ trsl,
                          const float* __restrict__ scale)
{
    int idx = blockIdx.x * blockDim.x + threadIdx.x;
    if (idx < CS * PW) {
        int r = idx / PW, c = idx - r * PW;
        float v;
        if      (c < 192)  v = Wq [r*192 + c];
        else if (c < 384)  v = Wk [r*192 + c-192];
        else if (c < 576)  v = Wv [r*192 + c-384];
        else if (c < 720)  v = Wqp[r*144 + c-576];
        else if (c < 864)  v = Wkp[r*144 + c-720];
        else               v = Wvp[r*288 + c-864];
        g_Wcat[idx] = v;
    }
    if (idx < LL) {
        float w = quat[idx*4], x = quat[idx*4+1], y = quat[idx*4+2], z = quat[idx*4+3];
        float inv = rsqrtf(w*w + x*x + y*y + z*z);
        w *= inv; x *= inv; y *= inv; z *= inv;
        float* R = g_R + idx*9;
        R[0]=1.f-2.f*(y*y+z*z); R[1]=2.f*(x*y-w*z);     R[2]=2.f*(x*z+w*y);
        R[3]=2.f*(x*y+w*z);     R[4]=1.f-2.f*(x*x+z*z); R[5]=2.f*(y*z-w*x);
        R[6]=2.f*(x*z-w*y);     R[7]=2.f*(y*z+w*x);     R[8]=1.f-2.f*(x*x+y*y);
        g_t[idx*3]=trsl[idx*3]; g_t[idx*3+1]=trsl[idx*3+1]; g_t[idx*3+2]=trsl[idx*3+2];
    }
    if (idx < 12) g_coef[idx] = 0.5f * WCC * log1pf(expf(scale[idx]));
}

__global__ void transform()
{
    int i = blockIdx.x, pt = threadIdx.x;   // 384 threads
    if (pt < 192) g_kT[pt * LL + i] = g_proj[(size_t)i*PW + 192 + pt];
    else          g_vT[(pt-192) * LL + i] = g_proj[(size_t)i*PW + 384 + (pt-192)];
    if (pt >= 192) return;
    const float* R = g_R + i*9;
    const float* t = g_t + i*3;
    const float* src;
    if (pt < 48)      src = g_proj + (size_t)i*PW + 576 + pt*3;
    else if (pt < 96) src = g_proj + (size_t)i*PW + 720 + (pt-48)*3;
    else              src = g_proj + (size_t)i*PW + 864 + (pt-96)*3;
    float px = src[0], py = src[1], pz = src[2];
    float ox = R[0]*px + R[1]*py + R[2]*pz + t[0];
    float oy = R[3]*px + R[4]*py + R[5]*pz + t[1];
    float oz = R[6]*px + R[7]*py + R[8]*pz + t[2];
    if (pt < 48) {
        float* d = g_qpp + i*144 + pt*3;
        d[0] = ox; d[1] = oy; d[2] = oz;
    } else if (pt < 96) {
        int p = pt - 48;
        g_kppT[(p*3+0)*LL + i] = ox;
        g_kppT[(p*3+1)*LL + i] = oy;
        g_kppT[(p*3+2)*LL + i] = oz;
    } else {
        int p = pt - 96;
        g_vppT[(p*3+0)*LL + i] = ox;
        g_vppT[(p*3+1)*LL + i] = oy;
        g_vppT[(p*3+2)*LL + i] = oz;
    }
}

// bias GEMM: g_Bt[h][row] = (z @ Wb)[row][h],  row = i*512+j
__global__ __launch_bounds__(256) void bias_gemm(const float* __restrict__ z,
                                                 const float* __restrict__ Wb)
{
    __shared__ float sWb[CZ * 12];
    __shared__ float sAz[256][33];
    int row0 = blockIdx.x * 256;
    int tid = threadIdx.x;
    int q = tid & 63, hp = tid >> 6;

    for (int x = tid; x < CZ*12; x += 256) sWb[x] = Wb[x];

    float acc[4][3] = {};
    for (int ch = 0; ch < 8; ch++) {
        __syncthreads();
        #pragma unroll
        for (int t = 0; t < 8; t++) {
            int idx = tid + t * 256;
            int row = idx >> 3, c4 = idx & 7;
            float4 v = *(const float4*)(z + (size_t)(row0 + row) * CZ + ch*32 + c4*4);
            sAz[row][c4*4+0] = v.x; sAz[row][c4*4+1] = v.y;
            sAz[row][c4*4+2] = v.z; sAz[row][c4*4+3] = v.w;
        }
        __syncthreads();
        #pragma unroll 8
        for (int c = 0; c < 32; c++) {
            float w0 = sWb[(ch*32+c)*12 + hp*3 + 0];
            float w1 = sWb[(ch*32+c)*12 + hp*3 + 1];
            float w2 = sWb[(ch*32+c)*12 + hp*3 + 2];
            #pragma unroll
            for (int r = 0; r < 4; r++) {
                float a = sAz[q + 64*r][c];
                acc[r][0] = fmaf(a, w0, acc[r][0]);
                acc[r][1] = fmaf(a, w1, acc[r][1]);
                acc[r][2] = fmaf(a, w2, acc[r][2]);
            }
        }
    }
    #pragma unroll
    for (int r = 0; r < 4; r++) {
        int row = row0 + q + 64*r;
        #pragma unroll
        for (int hh = 0; hh < 3; hh++)
            g_Bt[(size_t)(hp*3+hh) * (LL*LL) + row] = acc[r][hh];
    }
}

// 64x64 tile SGEMM, 256 threads, 4x4 per thread, split-K along gridDim.z
__global__ __launch_bounds__(256) void gemm64(const float* __restrict__ A,
                                              const float* __restrict__ B,
                                              float* __restrict__ C,
                                              int lda, int ldb, int ldc,
                                              int kSlice, int K, int partStride)
{
    __shared__ float As[16][64];
    __shared__ float Bs[16][64];
    int n0 = blockIdx.x * 64, m0 = blockIdx.y * 64;
    int k0 = blockIdx.z * kSlice;
    int kend = min(K, k0 + kSlice);
    float* Cc = C + (size_t)blockIdx.z * partStride;
    int tid = threadIdx.x;
    int tx = tid & 15, ty = tid >> 4;
    int ar = tid >> 2, ac = (tid & 3) << 2;
    float acc[4][4] = {};
    for (int kt = k0; kt < kend; kt += 16) {
        float4 av = *(const float4*)(A + (size_t)(m0 + ar) * lda + kt + ac);
        As[ac+0][ar] = av.x; As[ac+1][ar] = av.y; As[ac+2][ar] = av.z; As[ac+3][ar] = av.w;
        *(float4*)&Bs[ty][tx << 2] = *(const float4*)(B + (size_t)(kt + ty) * ldb + n0 + (tx << 2));
        __syncthreads();
        #pragma unroll
        for (int kk = 0; kk < 16; kk++) {
            float4 a = *(float4*)&As[kk][ty << 2];
            float4 b = *(float4*)&Bs[kk][tx << 2];
            acc[0][0]=fmaf(a.x,b.x,acc[0][0]); acc[0][1]=fmaf(a.x,b.y,acc[0][1]);
            acc[0][2]=fmaf(a.x,b.z,acc[0][2]); acc[0][3]=fmaf(a.x,b.w,acc[0][3]);
            acc[1][0]=fmaf(a.y,b.x,acc[1][0]); acc[1][1]=fmaf(a.y,b.y,acc[1][1]);
            acc[1][2]=fmaf(a.y,b.z,acc[1][2]); acc[1][3]=fmaf(a.y,b.w,acc[1][3]);
            acc[2][0]=fmaf(a.z,b.x,acc[2][0]); acc[2][1]=fmaf(a.z,b.y,acc[2][1]);
            acc[2][2]=fmaf(a.z,b.z,acc[2][2]); acc[2][3]=fmaf(a.z,b.w,acc[2][3]);
            acc[3][0]=fmaf(a.w,b.x,acc[3][0]); acc[3][1]=fmaf(a.w,b.y,acc[3][1]);
            acc[3][2]=fmaf(a.w,b.z,acc[3][2]); acc[3][3]=fmaf(a.w,b.w,acc[3][3]);
        }
        __syncthreads();
    }
    #pragma unroll
    for (int r = 0; r < 4; r++)
        *(float4*)(Cc + (size_t)(m0 + (ty<<2) + r) * ldc + n0 + (tx<<2)) =
            make_float4(acc[r][0], acc[r][1], acc[r][2], acc[r][3]);
}

__global__ void combine(const float* __restrict__ parts, int nparts, int partStride,
                        const float* __restrict__ bias, float* __restrict__ out,
                        int total, int N)
{
    int idx = blockIdx.x * blockDim.x + threadIdx.x;
    if (idx >= total) return;
    float v = parts[idx];
    for (int p = 1; p < nparts; p++) v += parts[(size_t)p * partStride + idx];
    v += bias[idx % N];
    out[idx] = fmaxf(v, 0.f);
}

__global__ void ln_combine(const float* __restrict__ parts, int nparts, int partStride,
                           const float* __restrict__ bias, const float* __restrict__ resid,
                           const float* __restrict__ gg, const float* __restrict__ bb,
                           float* __restrict__ out)
{
    int i = blockIdx.x, t = threadIdx.x;   // 128 threads
    float v[3];
    #pragma unroll
    for (int k = 0; k < 3; k++) {
        int c = t + k * 128;
        size_t off = (size_t)i * CS + c;
        float x = parts[off];
        for (int p = 1; p < nparts; p++) x += parts[(size_t)p * partStride + off];
        v[k] = x + bias[c] + resid[off];
    }
    float s = v[0]+v[1]+v[2], q = v[0]*v[0]+v[1]*v[1]+v[2]*v[2];
    #pragma unroll
    for (int o = 16; o; o >>= 1) {
        s += __shfl_xor_sync(0xffffffffu, s, o);
        q += __shfl_xor_sync(0xffffffffu, q, o);
    }
    __shared__ float ss[4], sq[4];
    int w = t >> 5, lane = t & 31;
    if (lane == 0) { ss[w] = s; sq[w] = q; }
    __syncthreads();
    if (t == 0) {
        float S = ss[0]+ss[1]+ss[2]+ss[3], Q = sq[0]+sq[1]+sq[2]+sq[3];
        float m = S * (1.f/CS);
        ss[0] = m; sq[0] = rsqrtf(Q*(1.f/CS) - m*m + 1e-5f);
    }
    __syncthreads();
    float m = ss[0], r = sq[0];
    float* o = out + (size_t)i * CS;
    #pragma unroll
    for (int k = 0; k < 3; k++) {
        int c = t + k * 128;
        o[c] = (v[k]-m)*r*gg[c] + bb[c];
    }
}

// fused attention, bias precomputed; sA head-major [12][512]
__global__ __launch_bounds__(256) void attn(const float* __restrict__ z)
{
    __shared__ float sA[12 * LL];     // 24 KB
    __shared__ float sq[192], sqpp[144], sR[9], st3[3], scoef[12], sOVP[288];

    int i = blockIdx.x, tid = threadIdx.x;
    int lane = tid & 31, w = tid >> 5;
    const float* zrow = z + (size_t)i * LL * CZ;

    if (tid < 192) sq[tid] = g_proj[(size_t)i * PW + tid];
    if (tid < 144) sqpp[tid] = g_qpp[i*144 + tid];
    if (tid < 9)   sR[tid] = g_R[i*9 + tid];
    if (tid < 3)   st3[tid] = g_t[i*3 + tid];
    if (tid < 12)  scoef[tid] = g_coef[tid];
    __syncthreads();

    // ---- phase 1: logits, rows j=tid and j=tid+256 ----
    #pragma unroll
    for (int jj = 0; jj < 2; jj++) {
        int j = tid + jj * 256;
        #pragma unroll
        for (int h = 0; h < 12; h++) {
            float qk = 0.f;
            #pragma unroll
            for (int d = 0; d < 16; d++)
                qk = fmaf(sq[h*16+d], g_kT[(h*16+d)*LL + j], qk);
            float d2 = 0.f;
            #pragma unroll
            for (int e = 0; e < 12; e++) {
                float dd = sqpp[h*12+e] - g_kppT[(h*12+e)*LL + j];
                d2 = fmaf(dd, dd, d2);
            }
            float bh = g_Bt[(size_t)h * (LL*LL) + (size_t)i * LL + j];
            sA[h*LL + j] = WLL * (qk * 0.25f + bh - scoef[h] * d2);
        }
    }
    __syncthreads();

    // ---- softmax per head (rows contiguous) ----
    for (int h = w; h < 12; h += 8) {
        float* row = sA + h * LL;
        float m = -1e30f;
        for (int j = lane; j < LL; j += 32) m = fmaxf(m, row[j]);
        #pragma unroll
        for (int o = 16; o; o >>= 1) m = fmaxf(m, __shfl_xor_sync(0xffffffffu, m, o));
        float sum = 0.f;
        for (int j = lane; j < LL; j += 32) {
            float e = __expf(row[j] - m);
            row[j] = e; sum += e;
        }
        #pragma unroll
        for (int o = 16; o; o >>= 1) sum += __shfl_xor_sync(0xffffffffu, sum, o);
        float inv = 1.f / sum;
        for (int j = lane; j < LL; j += 32) row[j] *= inv;
    }
    __syncthreads();

    // ---- op = a^T @ z : unroll 8, MLP 8 ----
    {
        int h0 = (tid >> 6) * 3;
        int cc = (tid & 63) << 2;
        const float* a0p = sA + (h0+0) * LL;
        const float* a1p = sA + (h0+1) * LL;
        const float* a2p = sA + (h0+2) * LL;
        float acc[3][4] = {};
        for (int j = 0; j < LL; j += 8) {
            float4 zv[8];
            #pragma unroll
            for (int u = 0; u < 8; u++)
                zv[u] = *(const float4*)(zrow + (size_t)(j+u) * CZ + cc);
            float4 a0a = *(const float4*)(a0p + j), a0b = *(const float4*)(a0p + j + 4);
            float4 a1a = *(const float4*)(a1p + j), a1b = *(const float4*)(a1p + j + 4);
            float4 a2a = *(const float4*)(a2p + j), a2b = *(const float4*)(a2p + j + 4);
            float a0v[8] = {a0a.x,a0a.y,a0a.z,a0a.w, a0b.x,a0b.y,a0b.z,a0b.w};
            float a1v[8] = {a1a.x,a1a.y,a1a.z,a1a.w, a1b.x,a1b.y,a1b.z,a1b.w};
            float a2v[8] = {a2a.x,a2a.y,a2a.z,a2a.w, a2b.x,a2b.y,a2b.z,a2b.w};
            #pragma unroll
            for (int u = 0; u < 8; u++) {
                float4 zu = zv[u];
                acc[0][0]=fmaf(a0v[u],zu.x,acc[0][0]); acc[0][1]=fmaf(a0v[u],zu.y,acc[0][1]);
                acc[0][2]=fmaf(a0v[u],zu.z,acc[0][2]); acc[0][3]=fmaf(a0v[u],zu.w,acc[0][3]);
                acc[1][0]=fmaf(a1v[u],zu.x,acc[1][0]); acc[1][1]=fmaf(a1v[u],zu.y,acc[1][1]);
                acc[1][2]=fmaf(a1v[u],zu.z,acc[1][2]); acc[1][3]=fmaf(a1v[u],zu.w,acc[1][3]);
                acc[2][0]=fmaf(a2v[u],zu.x,acc[2][0]); acc[2][1]=fmaf(a2v[u],zu.y,acc[2][1]);
                acc[2][2]=fmaf(a2v[u],zu.z,acc[2][2]); acc[2][3]=fmaf(a2v[u],zu.w,acc[2][3]);
            }
        }
        float* orow = g_shid + (size_t)i * SH;
        #pragma unroll
        for (int hh = 0; hh < 3; hh++)
            *(float4*)(orow + (h0+hh)*304 + cc) =
                make_float4(acc[hh][0], acc[hh][1], acc[hh][2], acc[hh][3]);
    }

    // ---- ov (16) + ovp_g (24) per head, unroll 8 ----
    if (tid < 240) {
        int h = tid / 20, o = (tid % 20) * 2;
        const float* s0;
        if (o < 16) s0 = g_vT + (h*16+o)*LL;
        else        s0 = g_vppT + (h*24+o-16)*LL;
        const float* s1p = s0 + LL;
        const float* ap = sA + h * LL;
        float a0 = 0.f, a1 = 0.f;
        for (int j = 0; j < LL; j += 8) {
            float4 v0a = *(const float4*)(s0 + j),  v0b = *(const float4*)(s0 + j + 4);
            float4 v1a = *(const float4*)(s1p + j), v1b = *(const float4*)(s1p + j + 4);
            float4 aa  = *(const float4*)(ap + j),  ab  = *(const float4*)(ap + j + 4);
            a0 = fmaf(aa.x,v0a.x,fmaf(aa.y,v0a.y,fmaf(aa.z,v0a.z,fmaf(aa.w,v0a.w,a0))));
            a0 = fmaf(ab.x,v0b.x,fmaf(ab.y,v0b.y,fmaf(ab.z,v0b.z,fmaf(ab.w,v0b.w,a0))));
            a1 = fmaf(aa.x,v1a.x,fmaf(aa.y,v1a.y,fmaf(aa.z,v1a.z,fmaf(aa.w,v1a.w,a1))));
            a1 = fmaf(ab.x,v1b.x,fmaf(ab.y,v1b.y,fmaf(ab.z,v1b.z,fmaf(ab.w,v1b.w,a1))));
        }
        float* orow = g_shid + (size_t)i * SH + h * 304;
        if (o < 16) { orow[256+o] = a0; orow[257+o] = a1; }
        else        { sOVP[h*24 + o-16] = a0; sOVP[h*24 + o-15] = a1; }
    }
    __syncthreads();

    // ---- ovp = R^T (ovp_g - t), norms ----
    if (tid < 96) {
        int h = tid >> 3, vv = tid & 7;
        float gx = sOVP[h*24 + vv*3 + 0] - st3[0];
        float gy = sOVP[h*24 + vv*3 + 1] - st3[1];
        float gz = sOVP[h*24 + vv*3 + 2] - st3[2];
        float lx = sR[0]*gx + sR[3]*gy + sR[6]*gz;
        float ly = sR[1]*gx + sR[4]*gy + sR[7]*gz;
        float lz = sR[2]*gx + sR[5]*gy + sR[8]*gz;
        float* orow = g_shid + (size_t)i * SH + h * 304;
        orow[272 + vv*3 + 0] = lx;
        orow[272 + vv*3 + 1] = ly;
        orow[272 + vv*3 + 2] = lz;
        orow[296 + vv] = sqrtf(lx*lx + ly*ly + lz*lz);
    }
}

extern "C" void kernel_launch(void* const* d_in, const int* in_sizes, int n_in,
                              void* d_out, int out_size)
{
    const float* s    = (const float*)d_in[0];
    const float* z    = (const float*)d_in[1];
    const float* quat = (const float*)d_in[2];
    const float* trsl = (const float*)d_in[3];
    const float* Wq   = (const float*)d_in[4];
    const float* Wk   = (const float*)d_in[5];
    const float* Wv   = (const float*)d_in[6];
    const float* Wqp  = (const float*)d_in[7];
    const float* Wkp  = (const float*)d_in[8];
    const float* Wvp  = (const float*)d_in[9];
    const float* Wb   = (const float*)d_in[10];
    const float* Ws   = (const float*)d_in[11];
    const float* bs   = (const float*)d_in[12];
    const float* scale= (const float*)d_in[13];
    const float* g1   = (const float*)d_in[14];
    const float* b1   = (const float*)d_in[15];
    const float* Wm1  = (const float*)d_in[16];
    const float* bm1  = (const float*)d_in[17];
    const float* Wm2  = (const float*)d_in[18];
    const float* bm2  = (const float*)d_in[19];
    const float* Wm3  = (const float*)d_in[20];
    const float* bm3  = (const float*)d_in[21];
    const float* g2   = (const float*)d_in[22];
    const float* b2   = (const float*)d_in[23];
    float* out = (float*)d_out;

    void *pWcat, *pProj, *pShid, *pParts, *pS1, *pH1, *pH2;
    cudaGetSymbolAddress(&pWcat,  g_Wcat);
    cudaGetSymbolAddress(&pProj,  g_proj);
    cudaGetSymbolAddress(&pShid,  g_shid);
    cudaGetSymbolAddress(&pParts, g_parts);
    cudaGetSymbolAddress(&pS1,    g_s1);
    cudaGetSymbolAddress(&pH1,    g_h1);
    cudaGetSymbolAddress(&pH2,    g_h2);
    float* Wcat = (float*)pWcat;  float* proj = (float*)pProj;
    float* shid = (float*)pShid;  float* parts = (float*)pParts;
    float* s1 = (float*)pS1;      float* h1 = (float*)pH1;
    float* h2 = (float*)pH2;

    const int TOT = LL * CS;

    pack_prep<<<(CS*PW + 255)/256, 256>>>(Wq, Wk, Wv, Wqp, Wkp, Wvp, quat, trsl, scale);
    bias_gemm<<<(LL*LL)/256, 256>>>(z, Wb);
    gemm64<<<dim3(PW/64, LL/64, 1), 256>>>(s, Wcat, proj, CS, PW, PW, CS, CS, 0);
    transform<<<LL, 384>>>();
    attn<<<LL, 256>>>(z);
    gemm64<<<dim3(CS/64, LL/64, 4), 256>>>(shid, Ws, parts, SH, CS, CS, SH/4, SH, TOT);
    ln_combine<<<LL, 128>>>(parts, 4, TOT, bs, s, g1, b1, s1);
    gemm64<<<dim3(CS/64, LL/64, 3), 256>>>(s1, Wm1, parts, CS, CS, CS, CS/3, CS, TOT);
    combine<<<(TOT+255)/256, 256>>>(parts, 3, TOT, bm1, h1, TOT, CS);
    gemm64<<<dim3(CS/64, LL/64, 3), 256>>>(h1, Wm2, parts, CS, CS, CS, CS/3, CS, TOT);
    combine<<<(TOT+255)/256, 256>>>(parts, 3, TOT, bm2, h2, TOT, CS);
    gemm64<<<dim3(CS/64, LL/64, 3), 256>>>(h2, Wm3, parts, CS, CS, CS, CS/3, CS, TOT);
    ln_combine<<<LL, 128>>>(parts, 3, TOT, bm3, s1, g2, b2, out);
}

// round 8
// speedup vs baseline: 1.2682x; 1.0307x over previous
#include <cuda_runtime.h>
#include <math.h>

#define LL 512
#define CS 384
#define CZ 256
#define PW 1152
#define SH 3648
#define WLL 0.57735026918962576f
#define WCC 0.23570226039551584f

typedef unsigned long long u64;
__device__ __forceinline__ u64 dup2(float a){ u64 r; asm("mov.b64 %0,{%1,%1};" : "=l"(r) : "f"(a)); return r; }
__device__ __forceinline__ void ffma2(u64& d, u64 a, u64 b){ asm("fma.rn.f32x2 %0,%1,%2,%0;" : "+l"(d) : "l"(a), "l"(b)); }

__device__ float g_Wcat[CS * PW];
__device__ float g_proj[LL * PW];   // [q 0|k 192|v 384|qp 576|kp 720|vp 864]
__device__ float g_R[LL * 9];
__device__ float g_t[LL * 3];
__device__ float g_coef[12];
__device__ float g_qpp[LL * 144];
__device__ float g_kT[192 * LL];        // j-contiguous
__device__ float g_vT[192 * LL];        // j-contiguous
__device__ float g_kppT[144 * LL];      // j-contiguous
__device__ float g_vppT[288 * LL];      // j-contiguous
__device__ float g_Bt[12 * LL * LL];    // bias logits, head-major [h][i*512+j]
__device__ float g_A[LL * 12 * LL];     // softmaxed attention [i][h][j]
__device__ float g_shid[LL * SH];
__device__ float g_parts[4 * LL * CS];
__device__ float g_s1[LL * CS];
__device__ float g_h1[LL * CS];
__device__ float g_h2[LL * CS];

__global__ void pack_prep(const float* __restrict__ Wq, const float* __restrict__ Wk,
                          const float* __restrict__ Wv, const float* __restrict__ Wqp,
                          const float* __restrict__ Wkp, const float* __restrict__ Wvp,
                          const float* __restrict__ quat, const float* __restrict__ trsl,
                          const float* __restrict__ scale)
{
    int idx = blockIdx.x * blockDim.x + threadIdx.x;
    if (idx < CS * PW) {
        int r = idx / PW, c = idx - r * PW;
        float v;
        if      (c < 192)  v = Wq [r*192 + c];
        else if (c < 384)  v = Wk [r*192 + c-192];
        else if (c < 576)  v = Wv [r*192 + c-384];
        else if (c < 720)  v = Wqp[r*144 + c-576];
        else if (c < 864)  v = Wkp[r*144 + c-720];
        else               v = Wvp[r*288 + c-864];
        g_Wcat[idx] = v;
    }
    if (idx < LL) {
        float w = quat[idx*4], x = quat[idx*4+1], y = quat[idx*4+2], z = quat[idx*4+3];
        float inv = rsqrtf(w*w + x*x + y*y + z*z);
        w *= inv; x *= inv; y *= inv; z *= inv;
        float* R = g_R + idx*9;
        R[0]=1.f-2.f*(y*y+z*z); R[1]=2.f*(x*y-w*z);     R[2]=2.f*(x*z+w*y);
        R[3]=2.f*(x*y+w*z);     R[4]=1.f-2.f*(x*x+z*z); R[5]=2.f*(y*z-w*x);
        R[6]=2.f*(x*z-w*y);     R[7]=2.f*(y*z+w*x);     R[8]=1.f-2.f*(x*x+y*y);
        g_t[idx*3]=trsl[idx*3]; g_t[idx*3+1]=trsl[idx*3+1]; g_t[idx*3+2]=trsl[idx*3+2];
    }
    if (idx < 12) g_coef[idx] = 0.5f * WCC * log1pf(expf(scale[idx]));
}

__global__ void transform()
{
    int i = blockIdx.x, pt = threadIdx.x;   // 384 threads
    if (pt < 192) g_kT[pt * LL + i] = g_proj[(size_t)i*PW + 192 + pt];
    else          g_vT[(pt-192) * LL + i] = g_proj[(size_t)i*PW + 384 + (pt-192)];
    if (pt >= 192) return;
    const float* R = g_R + i*9;
    const float* t = g_t + i*3;
    const float* src;
    if (pt < 48)      src = g_proj + (size_t)i*PW + 576 + pt*3;
    else if (pt < 96) src = g_proj + (size_t)i*PW + 720 + (pt-48)*3;
    else              src = g_proj + (size_t)i*PW + 864 + (pt-96)*3;
    float px = src[0], py = src[1], pz = src[2];
    float ox = R[0]*px + R[1]*py + R[2]*pz + t[0];
    float oy = R[3]*px + R[4]*py + R[5]*pz + t[1];
    float oz = R[6]*px + R[7]*py + R[8]*pz + t[2];
    if (pt < 48) {
        float* d = g_qpp + i*144 + pt*3;
        d[0] = ox; d[1] = oy; d[2] = oz;
    } else if (pt < 96) {
        int p = pt - 48;
        g_kppT[(p*3+0)*LL + i] = ox;
        g_kppT[(p*3+1)*LL + i] = oy;
        g_kppT[(p*3+2)*LL + i] = oz;
    } else {
        int p = pt - 96;
        g_vppT[(p*3+0)*LL + i] = ox;
        g_vppT[(p*3+1)*LL + i] = oy;
        g_vppT[(p*3+2)*LL + i] = oz;
    }
}

// bias GEMM: g_Bt[h][row] = (z @ Wb)[row][h]
__global__ __launch_bounds__(256) void bias_gemm(const float* __restrict__ z,
                                                 const float* __restrict__ Wb)
{
    __shared__ float sWb[CZ * 12];
    __shared__ float sAz[256][33];
    int row0 = blockIdx.x * 256;
    int tid = threadIdx.x;
    int q = tid & 63, hp = tid >> 6;

    for (int x = tid; x < CZ*12; x += 256) sWb[x] = Wb[x];

    float acc[4][3] = {};
    for (int ch = 0; ch < 8; ch++) {
        __syncthreads();
        #pragma unroll
        for (int t = 0; t < 8; t++) {
            int idx = tid + t * 256;
            int row = idx >> 3, c4 = idx & 7;
            float4 v = *(const float4*)(z + (size_t)(row0 + row) * CZ + ch*32 + c4*4);
            sAz[row][c4*4+0] = v.x; sAz[row][c4*4+1] = v.y;
            sAz[row][c4*4+2] = v.z; sAz[row][c4*4+3] = v.w;
        }
        __syncthreads();
        #pragma unroll 8
        for (int c = 0; c < 32; c++) {
            float w0 = sWb[(ch*32+c)*12 + hp*3 + 0];
            float w1 = sWb[(ch*32+c)*12 + hp*3 + 1];
            float w2 = sWb[(ch*32+c)*12 + hp*3 + 2];
            #pragma unroll
            for (int r = 0; r < 4; r++) {
                float a = sAz[q + 64*r][c];
                acc[r][0] = fmaf(a, w0, acc[r][0]);
                acc[r][1] = fmaf(a, w1, acc[r][1]);
                acc[r][2] = fmaf(a, w2, acc[r][2]);
            }
        }
    }
    #pragma unroll
    for (int r = 0; r < 4; r++) {
        int row = row0 + q + 64*r;
        #pragma unroll
        for (int hh = 0; hh < 3; hh++)
            g_Bt[(size_t)(hp*3+hh) * (LL*LL) + row] = acc[r][hh];
    }
}

// 64x64 tile SGEMM with packed f32x2 accumulation
__global__ __launch_bounds__(256) void gemm64(const float* __restrict__ A,
                                              const float* __restrict__ B,
                                              float* __restrict__ C,
                                              int lda, int ldb, int ldc,
                                              int kSlice, int K, int partStride)
{
    __shared__ float As[16][64];
    __shared__ float Bs[16][64];
    int n0 = blockIdx.x * 64, m0 = blockIdx.y * 64;
    int k0 = blockIdx.z * kSlice;
    int kend = min(K, k0 + kSlice);
    float* Cc = C + (size_t)blockIdx.z * partStride;
    int tid = threadIdx.x;
    int tx = tid & 15, ty = tid >> 4;
    int ar = tid >> 2, ac = (tid & 3) << 2;
    u64 acc[4][2] = {};
    for (int kt = k0; kt < kend; kt += 16) {
        float4 av = *(const float4*)(A + (size_t)(m0 + ar) * lda + kt + ac);
        As[ac+0][ar] = av.x; As[ac+1][ar] = av.y; As[ac+2][ar] = av.z; As[ac+3][ar] = av.w;
        *(float4*)&Bs[ty][tx << 2] = *(const float4*)(B + (size_t)(kt + ty) * ldb + n0 + (tx << 2));
        __syncthreads();
        #pragma unroll
        for (int kk = 0; kk < 16; kk++) {
            float4 a = *(float4*)&As[kk][ty << 2];
            ulonglong2 b2 = *(ulonglong2*)&Bs[kk][tx << 2];
            u64 d0 = dup2(a.x), d1 = dup2(a.y), d2 = dup2(a.z), d3 = dup2(a.w);
            ffma2(acc[0][0], b2.x, d0); ffma2(acc[0][1], b2.y, d0);
            ffma2(acc[1][0], b2.x, d1); ffma2(acc[1][1], b2.y, d1);
            ffma2(acc[2][0], b2.x, d2); ffma2(acc[2][1], b2.y, d2);
            ffma2(acc[3][0], b2.x, d3); ffma2(acc[3][1], b2.y, d3);
        }
        __syncthreads();
    }
    #pragma unroll
    for (int r = 0; r < 4; r++) {
        ulonglong2 st; st.x = acc[r][0]; st.y = acc[r][1];
        *(ulonglong2*)(Cc + (size_t)(m0 + (ty<<2) + r) * ldc + n0 + (tx<<2)) = st;
    }
}

__global__ void combine(const float* __restrict__ parts, int nparts, int partStride,
                        const float* __restrict__ bias, float* __restrict__ out,
                        int total, int N)
{
    int idx = blockIdx.x * blockDim.x + threadIdx.x;
    if (idx >= total) return;
    float v = parts[idx];
    for (int p = 1; p < nparts; p++) v += parts[(size_t)p * partStride + idx];
    v += bias[idx % N];
    out[idx] = fmaxf(v, 0.f);
}

__global__ void ln_combine(const float* __restrict__ parts, int nparts, int partStride,
                           const float* __restrict__ bias, const float* __restrict__ resid,
                           const float* __restrict__ gg, const float* __restrict__ bb,
                           float* __restrict__ out)
{
    int i = blockIdx.x, t = threadIdx.x;   // 128 threads
    float v[3];
    #pragma unroll
    for (int k = 0; k < 3; k++) {
        int c = t + k * 128;
        size_t off = (size_t)i * CS + c;
        float x = parts[off];
        for (int p = 1; p < nparts; p++) x += parts[(size_t)p * partStride + off];
        v[k] = x + bias[c] + resid[off];
    }
    float s = v[0]+v[1]+v[2], q = v[0]*v[0]+v[1]*v[1]+v[2]*v[2];
    #pragma unroll
    for (int o = 16; o; o >>= 1) {
        s += __shfl_xor_sync(0xffffffffu, s, o);
        q += __shfl_xor_sync(0xffffffffu, q, o);
    }
    __shared__ float ss[4], sq[4];
    int w = t >> 5, lane = t & 31;
    if (lane == 0) { ss[w] = s; sq[w] = q; }
    __syncthreads();
    if (t == 0) {
        float S = ss[0]+ss[1]+ss[2]+ss[3], Q = sq[0]+sq[1]+sq[2]+sq[3];
        float m = S * (1.f/CS);
        ss[0] = m; sq[0] = rsqrtf(Q*(1.f/CS) - m*m + 1e-5f);
    }
    __syncthreads();
    float m = ss[0], r = sq[0];
    float* o = out + (size_t)i * CS;
    #pragma unroll
    for (int k = 0; k < 3; k++) {
        int c = t + k * 128;
        o[c] = (v[k]-m)*r*gg[c] + bb[c];
    }
}

// attention part 1: logits + softmax + ov/ovp; writes weights to g_A
__global__ __launch_bounds__(256) void attn()
{
    __shared__ float sA[12 * LL];     // 24 KB
    __shared__ float sq[192], sqpp[144], sR[9], st3[3], scoef[12], sOVP[288];

    int i = blockIdx.x, tid = threadIdx.x;
    int lane = tid & 31, w = tid >> 5;

    if (tid < 192) sq[tid] = g_proj[(size_t)i * PW + tid];
    if (tid < 144) sqpp[tid] = g_qpp[i*144 + tid];
    if (tid < 9)   sR[tid] = g_R[i*9 + tid];
    if (tid < 3)   st3[tid] = g_t[i*3 + tid];
    if (tid < 12)  scoef[tid] = g_coef[tid];
    __syncthreads();

    // ---- logits, rows j=tid and j=tid+256 ----
    #pragma unroll
    for (int jj = 0; jj < 2; jj++) {
        int j = tid + jj * 256;
        #pragma unroll
        for (int h = 0; h < 12; h++) {
            float qk = 0.f;
            #pragma unroll
            for (int d = 0; d < 16; d++)
                qk = fmaf(sq[h*16+d], g_kT[(h*16+d)*LL + j], qk);
            float d2 = 0.f;
            #pragma unroll
            for (int e = 0; e < 12; e++) {
                float dd = sqpp[h*12+e] - g_kppT[(h*12+e)*LL + j];
                d2 = fmaf(dd, dd, d2);
            }
            float bh = g_Bt[(size_t)h * (LL*LL) + (size_t)i * LL + j];
            sA[h*LL + j] = WLL * (qk * 0.25f + bh - scoef[h] * d2);
        }
    }
    __syncthreads();

    // ---- softmax per head ----
    for (int h = w; h < 12; h += 8) {
        float* row = sA + h * LL;
        float m = -1e30f;
        for (int j = lane; j < LL; j += 32) m = fmaxf(m, row[j]);
        #pragma unroll
        for (int o = 16; o; o >>= 1) m = fmaxf(m, __shfl_xor_sync(0xffffffffu, m, o));
        float sum = 0.f;
        for (int j = lane; j < LL; j += 32) {
            float e = __expf(row[j] - m);
            row[j] = e; sum += e;
        }
        #pragma unroll
        for (int o = 16; o; o >>= 1) sum += __shfl_xor_sync(0xffffffffu, sum, o);
        float inv = 1.f / sum;
        for (int j = lane; j < LL; j += 32) row[j] *= inv;
    }
    __syncthreads();

    // ---- export weights for op_gemm ----
    {
        float* ga = g_A + (size_t)i * 12 * LL;
        for (int x = tid * 4; x < 12 * LL; x += 1024)
            *(float4*)(ga + x) = *(const float4*)&sA[x];
    }

    // ---- ov (16) + ovp_g (24) per head, unroll 8 ----
    if (tid < 240) {
        int h = tid / 20, o = (tid % 20) * 2;
        const float* s0;
        if (o < 16) s0 = g_vT + (h*16+o)*LL;
        else        s0 = g_vppT + (h*24+o-16)*LL;
        const float* s1p = s0 + LL;
        const float* ap = sA + h * LL;
        float a0 = 0.f, a1 = 0.f;
        for (int j = 0; j < LL; j += 8) {
            float4 v0a = *(const float4*)(s0 + j),  v0b = *(const float4*)(s0 + j + 4);
            float4 v1a = *(const float4*)(s1p + j), v1b = *(const float4*)(s1p + j + 4);
            float4 aa  = *(const float4*)(ap + j),  ab  = *(const float4*)(ap + j + 4);
            a0 = fmaf(aa.x,v0a.x,fmaf(aa.y,v0a.y,fmaf(aa.z,v0a.z,fmaf(aa.w,v0a.w,a0))));
            a0 = fmaf(ab.x,v0b.x,fmaf(ab.y,v0b.y,fmaf(ab.z,v0b.z,fmaf(ab.w,v0b.w,a0))));
            a1 = fmaf(aa.x,v1a.x,fmaf(aa.y,v1a.y,fmaf(aa.z,v1a.z,fmaf(aa.w,v1a.w,a1))));
            a1 = fmaf(ab.x,v1b.x,fmaf(ab.y,v1b.y,fmaf(ab.z,v1b.z,fmaf(ab.w,v1b.w,a1))));
        }
        float* orow = g_shid + (size_t)i * SH + h * 304;
        if (o < 16) { orow[256+o] = a0; orow[257+o] = a1; }
        else        { sOVP[h*24 + o-16] = a0; sOVP[h*24 + o-15] = a1; }
    }
    __syncthreads();

    // ---- ovp = R^T (ovp_g - t), norms ----
    if (tid < 96) {
        int h = tid >> 3, vv = tid & 7;
        float gx = sOVP[h*24 + vv*3 + 0] - st3[0];
        float gy = sOVP[h*24 + vv*3 + 1] - st3[1];
        float gz = sOVP[h*24 + vv*3 + 2] - st3[2];
        float lx = sR[0]*gx + sR[3]*gy + sR[6]*gz;
        float ly = sR[1]*gx + sR[4]*gy + sR[7]*gz;
        float lz = sR[2]*gx + sR[5]*gy + sR[8]*gz;
        float* orow = g_shid + (size_t)i * SH + h * 304;
        orow[272 + vv*3 + 0] = lx;
        orow[272 + vv*3 + 1] = ly;
        orow[272 + vv*3 + 2] = lz;
        orow[296 + vv] = sqrtf(lx*lx + ly*ly + lz*lz);
    }
}

// op = a^T @ z per query row, packed f32x2; one CTA per i
__global__ __launch_bounds__(256) void op_gemm(const float* __restrict__ z)
{
    __shared__ float sA[12 * LL];   // 24 KB
    int i = blockIdx.x, tid = threadIdx.x;
    const float* ga = g_A + (size_t)i * 12 * LL;
    for (int x = tid * 4; x < 12 * LL; x += 1024)
        *(float4*)&sA[x] = *(const float4*)(ga + x);
    __syncthreads();

    int h0 = (tid >> 6) * 3;
    int cc = (tid & 63) << 2;
    const float* zp = z + (size_t)i * LL * CZ + cc;
    const float* a0p = sA + (h0+0) * LL;
    const float* a1p = sA + (h0+1) * LL;
    const float* a2p = sA + (h0+2) * LL;
    u64 acc[3][2] = {};
    for (int j = 0; j < LL; j += 4) {
        ulonglong2 zv[4];
        #pragma unroll
        for (int u = 0; u < 4; u++)
            zv[u] = *(const ulonglong2*)(zp + (size_t)(j+u) * CZ);
        float4 a0 = *(const float4*)(a0p + j);
        float4 a1 = *(const float4*)(a1p + j);
        float4 a2 = *(const float4*)(a2p + j);
        float a0v[4] = {a0.x,a0.y,a0.z,a0.w};
        float a1v[4] = {a1.x,a1.y,a1.z,a1.w};
        float a2v[4] = {a2.x,a2.y,a2.z,a2.w};
        #pragma unroll
        for (int u = 0; u < 4; u++) {
            u64 d0 = dup2(a0v[u]), d1 = dup2(a1v[u]), d2 = dup2(a2v[u]);
            ffma2(acc[0][0], zv[u].x, d0); ffma2(acc[0][1], zv[u].y, d0);
            ffma2(acc[1][0], zv[u].x, d1); ffma2(acc[1][1], zv[u].y, d1);
            ffma2(acc[2][0], zv[u].x, d2); ffma2(acc[2][1], zv[u].y, d2);
        }
    }
    float* orow = g_shid + (size_t)i * SH;
    #pragma unroll
    for (int hh = 0; hh < 3; hh++) {
        ulonglong2 st; st.x = acc[hh][0]; st.y = acc[hh][1];
        *(ulonglong2*)(orow + (h0+hh)*304 + cc) = st;
    }
}

extern "C" void kernel_launch(void* const* d_in, const int* in_sizes, int n_in,
                              void* d_out, int out_size)
{
    const float* s    = (const float*)d_in[0];
    const float* z    = (const float*)d_in[1];
    const float* quat = (const float*)d_in[2];
    const float* trsl = (const float*)d_in[3];
    const float* Wq   = (const float*)d_in[4];
    const float* Wk   = (const float*)d_in[5];
    const float* Wv   = (const float*)d_in[6];
    const float* Wqp  = (const float*)d_in[7];
    const float* Wkp  = (const float*)d_in[8];
    const float* Wvp  = (const float*)d_in[9];
    const float* Wb   = (const float*)d_in[10];
    const float* Ws   = (const float*)d_in[11];
    const float* bs   = (const float*)d_in[12];
    const float* scale= (const float*)d_in[13];
    const float* g1   = (const float*)d_in[14];
    const float* b1   = (const float*)d_in[15];
    const float* Wm1  = (const float*)d_in[16];
    const float* bm1  = (const float*)d_in[17];
    const float* Wm2  = (const float*)d_in[18];
    const float* bm2  = (const float*)d_in[19];
    const float* Wm3  = (const float*)d_in[20];
    const float* bm3  = (const float*)d_in[21];
    const float* g2   = (const float*)d_in[22];
    const float* b2   = (const float*)d_in[23];
    float* out = (float*)d_out;

    void *pWcat, *pProj, *pShid, *pParts, *pS1, *pH1, *pH2;
    cudaGetSymbolAddress(&pWcat,  g_Wcat);
    cudaGetSymbolAddress(&pProj,  g_proj);
    cudaGetSymbolAddress(&pShid,  g_shid);
    cudaGetSymbolAddress(&pParts, g_parts);
    cudaGetSymbolAddress(&pS1,    g_s1);
    cudaGetSymbolAddress(&pH1,    g_h1);
    cudaGetSymbolAddress(&pH2,    g_h2);
    float* Wcat = (float*)pWcat;  float* proj = (float*)pProj;
    float* shid = (float*)pShid;  float* parts = (float*)pParts;
    float* s1 = (float*)pS1;      float* h1 = (float*)pH1;
    float* h2 = (float*)pH2;

    const int TOT = LL * CS;

    pack_prep<<<(CS*PW + 255)/256, 256>>>(Wq, Wk, Wv, Wqp, Wkp, Wvp, quat, trsl, scale);
    bias_gemm<<<(LL*LL)/256, 256>>>(z, Wb);
    gemm64<<<dim3(PW/64, LL/64, 1), 256>>>(s, Wcat, proj, CS, PW, PW, CS, CS, 0);
    transform<<<LL, 384>>>();
    attn<<<LL, 256>>>();
    op_gemm<<<LL, 256>>>(z);
    gemm64<<<dim3(CS/64, LL/64, 4), 256>>>(shid, Ws, parts, SH, CS, CS, SH/4, SH, TOT);
    ln_combine<<<LL, 128>>>(parts, 4, TOT, bs, s, g1, b1, s1);
    gemm64<<<dim3(CS/64, LL/64, 3), 256>>>(s1, Wm1, parts, CS, CS, CS, CS/3, CS, TOT);
    combine<<<(TOT+255)/256, 256>>>(parts, 3, TOT, bm1, h1, TOT, CS);
    gemm64<<<dim3(CS/64, LL/64, 3), 256>>>(h1, Wm2, parts, CS, CS, CS, CS/3, CS, TOT);
    combine<<<(TOT+255)/256, 256>>>(parts, 3, TOT, bm2, h2, TOT, CS);
    gemm64<<<dim3(CS/64, LL/64, 3), 256>>>(h2, Wm3, parts, CS, CS, CS, CS/3, CS, TOT);
    ln_combine<<<LL, 128>>>(parts, 3, TOT, bm3, s1, g2, b2, out);
}

// round 11
// speedup vs baseline: 1.3471x; 1.0622x over previous
#include <cuda_runtime.h>
#include <math.h>

#define LL 512
#define CS 384
#define CZ 256
#define PW 1152
#define SH 3648
#define WLL 0.57735026918962576f
#define WCC 0.23570226039551584f

typedef unsigned long long u64;
__device__ __forceinline__ u64 dup2(float a){ u64 r; asm("mov.b64 %0,{%1,%1};" : "=l"(r) : "f"(a)); return r; }
__device__ __forceinline__ u64 pack2(float lo, float hi){ u64 r; asm("mov.b64 %0,{%1,%2};" : "=l"(r) : "f"(lo), "f"(hi)); return r; }
__device__ __forceinline__ void unpack2(u64 v, float& lo, float& hi){ asm("mov.b64 {%0,%1},%2;" : "=f"(lo), "=f"(hi) : "l"(v)); }
__device__ __forceinline__ void ffma2(u64& d, u64 a, u64 b){ asm("fma.rn.f32x2 %0,%1,%2,%0;" : "+l"(d) : "l"(a), "l"(b)); }

__device__ float g_Wcat[CS * PW];
__device__ float g_proj[LL * PW];   // [q 0|k 192|v 384|qp 576|kp 720|vp 864]
__device__ float g_R[LL * 9];
__device__ float g_t[LL * 3];
__device__ float g_coef[12];
__device__ float g_qpp[LL * 144];
__device__ float g_kT[192 * LL];
__device__ float g_vT[192 * LL];
__device__ float g_kppT[144 * LL];
__device__ float g_vppT[288 * LL];
__device__ float g_Bt[12 * LL * LL];    // bias logits, head-major [h][i*512+j]
__device__ float g_A[LL * 12 * LL];     // softmaxed attention [i][h][j]
__device__ float g_shid[LL * SH];
__device__ float g_parts[6 * LL * CS];  // == 2 * LL * PW
__device__ float g_s1[LL * CS];
__device__ float g_h1[LL * CS];
__device__ float g_h2[LL * CS];

__global__ void pack_prep(const float* __restrict__ Wq, const float* __restrict__ Wk,
                          const float* __restrict__ Wv, const float* __restrict__ Wqp,
                          const float* __restrict__ Wkp, const float* __restrict__ Wvp,
                          const float* __restrict__ quat, const float* __restrict__ trsl,
                          const float* __restrict__ scale)
{
    int idx = blockIdx.x * blockDim.x + threadIdx.x;
    if (idx < CS * PW) {
        int r = idx / PW, c = idx - r * PW;
        float v;
        if      (c < 192)  v = Wq [r*192 + c];
        else if (c < 384)  v = Wk [r*192 + c-192];
        else if (c < 576)  v = Wv [r*192 + c-384];
        else if (c < 720)  v = Wqp[r*144 + c-576];
        else if (c < 864)  v = Wkp[r*144 + c-720];
        else               v = Wvp[r*288 + c-864];
        g_Wcat[idx] = v;
    }
    if (idx < LL) {
        float w = quat[idx*4], x = quat[idx*4+1], y = quat[idx*4+2], z = quat[idx*4+3];
        float inv = rsqrtf(w*w + x*x + y*y + z*z);
        w *= inv; x *= inv; y *= inv; z *= inv;
        float* R = g_R + idx*9;
        R[0]=1.f-2.f*(y*y+z*z); R[1]=2.f*(x*y-w*z);     R[2]=2.f*(x*z+w*y);
        R[3]=2.f*(x*y+w*z);     R[4]=1.f-2.f*(x*x+z*z); R[5]=2.f*(y*z-w*x);
        R[6]=2.f*(x*z-w*y);     R[7]=2.f*(y*z+w*x);     R[8]=1.f-2.f*(x*x+y*y);
        g_t[idx*3]=trsl[idx*3]; g_t[idx*3+1]=trsl[idx*3+1]; g_t[idx*3+2]=trsl[idx*3+2];
    }
    if (idx < 12) g_coef[idx] = 0.5f * WCC * log1pf(expf(scale[idx]));
}

__global__ void transform()
{
    int i = blockIdx.x, pt = threadIdx.x;   // 384 threads
    if (pt < 192) g_kT[pt * LL + i] = g_proj[(size_t)i*PW + 192 + pt];
    else          g_vT[(pt-192) * LL + i] = g_proj[(size_t)i*PW + 384 + (pt-192)];
    if (pt >= 192) return;
    const float* R = g_R + i*9;
    const float* t = g_t + i*3;
    const float* src;
    if (pt < 48)      src = g_proj + (size_t)i*PW + 576 + pt*3;
    else if (pt < 96) src = g_proj + (size_t)i*PW + 720 + (pt-48)*3;
    else              src = g_proj + (size_t)i*PW + 864 + (pt-96)*3;
    float px = src[0], py = src[1], pz = src[2];
    float ox = R[0]*px + R[1]*py + R[2]*pz + t[0];
    float oy = R[3]*px + R[4]*py + R[5]*pz + t[1];
    float oz = R[6]*px + R[7]*py + R[8]*pz + t[2];
    if (pt < 48) {
        float* d = g_qpp + i*144 + pt*3;
        d[0] = ox; d[1] = oy; d[2] = oz;
    } else if (pt < 96) {
        int p = pt - 48;
        g_kppT[(p*3+0)*LL + i] = ox;
        g_kppT[(p*3+1)*LL + i] = oy;
        g_kppT[(p*3+2)*LL + i] = oz;
    } else {
        int p = pt - 96;
        g_vppT[(p*3+0)*LL + i] = ox;
        g_vppT[(p*3+1)*LL + i] = oy;
        g_vppT[(p*3+2)*LL + i] = oz;
    }
}

// bias GEMM (f32x2): g_Bt[h][row] = (z @ Wb)[row][h]; head pairs
__global__ __launch_bounds__(256) void bias_gemm(const float* __restrict__ z,
                                                 const float* __restrict__ Wb)
{
    __shared__ u64 sW[CZ][6];           // [c][pair] 12 KB
    __shared__ float sAz[256][33];      // 33.8 KB
    int row0 = blockIdx.x * 256;
    int tid = threadIdx.x;
    int q = tid & 127, hp = tid >> 7;   // 2 head groups of 6 heads (3 pairs)

    for (int x = tid; x < CZ*6; x += 256) {
        int c = x / 6, p = x - c*6;
        sW[c][p] = pack2(Wb[c*12 + 2*p], Wb[c*12 + 2*p + 1]);
    }

    u64 acc0[3] = {}, acc1[3] = {};
    for (int ch = 0; ch < 8; ch++) {
        __syncthreads();
        #pragma unroll
        for (int t = 0; t < 8; t++) {
            int idx = tid + t * 256;
            int row = idx >> 3, c4 = idx & 7;
            float4 v = *(const float4*)(z + (size_t)(row0 + row) * CZ + ch*32 + c4*4);
            sAz[row][c4*4+0] = v.x; sAz[row][c4*4+1] = v.y;
            sAz[row][c4*4+2] = v.z; sAz[row][c4*4+3] = v.w;
        }
        __syncthreads();
        #pragma unroll 4
        for (int c = 0; c < 32; c++) {
            int cc = ch*32 + c;
            u64 w0 = sW[cc][hp*3+0], w1 = sW[cc][hp*3+1], w2 = sW[cc][hp*3+2];
            u64 d0 = dup2(sAz[q][c]);
            u64 d1 = dup2(sAz[q+128][c]);
            ffma2(acc0[0], d0, w0); ffma2(acc0[1], d0, w1); ffma2(acc0[2], d0, w2);
            ffma2(acc1[0], d1, w0); ffma2(acc1[1], d1, w1); ffma2(acc1[2], d1, w2);
        }
    }
    #pragma unroll
    for (int p = 0; p < 3; p++) {
        float lo, hi;
        unpack2(acc0[p], lo, hi);
        g_Bt[(size_t)(hp*6+2*p  )*(LL*LL) + row0 + q] = lo;
        g_Bt[(size_t)(hp*6+2*p+1)*(LL*LL) + row0 + q] = hi;
        unpack2(acc1[p], lo, hi);
        g_Bt[(size_t)(hp*6+2*p  )*(LL*LL) + row0 + q + 128] = lo;
        g_Bt[(size_t)(hp*6+2*p+1)*(LL*LL) + row0 + q + 128] = hi;
    }
}

// 128x64 tile GEMM, 256 threads, 8x4/thread, A pre-duplicated f32x2 in smem
__global__ __launch_bounds__(256) void gemm128(const float* __restrict__ A,
                                               const float* __restrict__ B,
                                               float* __restrict__ C,
                                               int lda, int ldb, int ldc,
                                               int kSlice, int K, int partStride)
{
    __shared__ u64 As[16][128];     // duplicated pairs, 16 KB
    __shared__ float Bs[16][64];    // 4 KB
    int n0 = blockIdx.x * 64, m0 = blockIdx.y * 128;
    int k0 = blockIdx.z * kSlice;
    int kend = min(K, k0 + kSlice);
    float* Cc = C + (size_t)blockIdx.z * partStride;
    int tid = threadIdx.x;
    int tx = tid & 15, ty = tid >> 4;
    u64 acc[8][2] = {};
    for (int kt = k0; kt < kend; kt += 16) {
        #pragma unroll
        for (int half = 0; half < 2; half++) {
            int f = tid + half * 256;
            int row = f >> 2, kq = (f & 3) << 2;
            float4 av = *(const float4*)(A + (size_t)(m0 + row) * lda + kt + kq);
            As[kq+0][row] = dup2(av.x);
            As[kq+1][row] = dup2(av.y);
            As[kq+2][row] = dup2(av.z);
            As[kq+3][row] = dup2(av.w);
        }
        {
            int k = tid >> 4, nq = (tid & 15) << 2;
            *(float4*)&Bs[k][nq] = *(const float4*)(B + (size_t)(kt + k) * ldb + n0 + nq);
        }
        __syncthreads();
        #pragma unroll
        for (int kk = 0; kk < 16; kk++) {
            u64 a[8];
            *(ulonglong2*)&a[0] = *(ulonglong2*)&As[kk][ty*8+0];
            *(ulonglong2*)&a[2] = *(ulonglong2*)&As[kk][ty*8+2];
            *(ulonglong2*)&a[4] = *(ulonglong2*)&As[kk][ty*8+4];
            *(ulonglong2*)&a[6] = *(ulonglong2*)&As[kk][ty*8+6];
            ulonglong2 b2 = *(ulonglong2*)&Bs[kk][tx << 2];
            #pragma unroll
            for (int m = 0; m < 8; m++) {
                ffma2(acc[m][0], a[m], b2.x);
                ffma2(acc[m][1], a[m], b2.y);
            }
        }
        __syncthreads();
    }
    #pragma unroll
    for (int m = 0; m < 8; m++) {
        ulonglong2 st; st.x = acc[m][0]; st.y = acc[m][1];
        *(ulonglong2*)(Cc + (size_t)(m0 + ty*8 + m) * ldc + n0 + (tx << 2)) = st;
    }
}

__global__ void combine(const float* __restrict__ parts, int nparts, int partStride,
                        const float* __restrict__ bias, float* __restrict__ out,
                        int total, int N, int relu)
{
    int idx = blockIdx.x * blockDim.x + threadIdx.x;
    if (idx >= total) return;
    float v = parts[idx];
    for (int p = 1; p < nparts; p++) v += parts[(size_t)p * partStride + idx];
    if (bias) v += bias[idx % N];
    if (relu) v = fmaxf(v, 0.f);
    out[idx] = v;
}

__global__ void ln_combine(const float* __restrict__ parts, int nparts, int partStride,
                           const float* __restrict__ bias, const float* __restrict__ resid,
                           const float* __restrict__ gg, const float* __restrict__ bb,
                           float* __restrict__ out)
{
    int i = blockIdx.x, t = threadIdx.x;   // 128 threads
    float v[3];
    #pragma unroll
    for (int k = 0; k < 3; k++) {
        int c = t + k * 128;
        size_t off = (size_t)i * CS + c;
        float x = parts[off];
        for (int p = 1; p < nparts; p++) x += parts[(size_t)p * partStride + off];
        v[k] = x + bias[c] + resid[off];
    }
    float s = v[0]+v[1]+v[2], q = v[0]*v[0]+v[1]*v[1]+v[2]*v[2];
    #pragma unroll
    for (int o = 16; o; o >>= 1) {
        s += __shfl_xor_sync(0xffffffffu, s, o);
        q += __shfl_xor_sync(0xffffffffu, q, o);
    }
    __shared__ float ss[4], sq[4];
    int w = t >> 5, lane = t & 31;
    if (lane == 0) { ss[w] = s; sq[w] = q; }
    __syncthreads();
    if (t == 0) {
        float S = ss[0]+ss[1]+ss[2]+ss[3], Q = sq[0]+sq[1]+sq[2]+sq[3];
        float m = S * (1.f/CS);
        ss[0] = m; sq[0] = rsqrtf(Q*(1.f/CS) - m*m + 1e-5f);
    }
    __syncthreads();
    float m = ss[0], r = sq[0];
    float* o = out + (size_t)i * CS;
    #pragma unroll
    for (int k = 0; k < 3; k++) {
        int c = t + k * 128;
        o[c] = (v[k]-m)*r*gg[c] + bb[c];
    }
}

// attention: logits + softmax + ov/ovp; writes weights to g_A
__global__ __launch_bounds__(256) void attn()
{
    __shared__ float sA[12 * LL];     // 24 KB
    __shared__ float sq[192], sqpp[144], sR[9], st3[3], scoef[12], sOVP[288];

    int i = blockIdx.x, tid = threadIdx.x;
    int lane = tid & 31, w = tid >> 5;

    if (tid < 192) sq[tid] = g_proj[(size_t)i * PW + tid];
    if (tid < 144) sqpp[tid] = g_qpp[i*144 + tid];
    if (tid < 9)   sR[tid] = g_R[i*9 + tid];
    if (tid < 3)   st3[tid] = g_t[i*3 + tid];
    if (tid < 12)  scoef[tid] = g_coef[tid];
    __syncthreads();

    #pragma unroll
    for (int jj = 0; jj < 2; jj++) {
        int j = tid + jj * 256;
        #pragma unroll
        for (int h = 0; h < 12; h++) {
            float qk = 0.f;
            #pragma unroll
            for (int d = 0; d < 16; d++)
                qk = fmaf(sq[h*16+d], g_kT[(h*16+d)*LL + j], qk);
            float d2 = 0.f;
            #pragma unroll
            for (int e = 0; e < 12; e++) {
                float dd = sqpp[h*12+e] - g_kppT[(h*12+e)*LL + j];
                d2 = fmaf(dd, dd, d2);
            }
            float bh = g_Bt[(size_t)h * (LL*LL) + (size_t)i * LL + j];
            sA[h*LL + j] = WLL * (qk * 0.25f + bh - scoef[h] * d2);
        }
    }
    __syncthreads();

    for (int h = w; h < 12; h += 8) {
        float* row = sA + h * LL;
        float m = -1e30f;
        for (int j = lane; j < LL; j += 32) m = fmaxf(m, row[j]);
        #pragma unroll
        for (int o = 16; o; o >>= 1) m = fmaxf(m, __shfl_xor_sync(0xffffffffu, m, o));
        float sum = 0.f;
        for (int j = lane; j < LL; j += 32) {
            float e = __expf(row[j] - m);
            row[j] = e; sum += e;
        }
        #pragma unroll
        for (int o = 16; o; o >>= 1) sum += __shfl_xor_sync(0xffffffffu, sum, o);
        float inv = 1.f / sum;
        for (int j = lane; j < LL; j += 32) row[j] *= inv;
    }
    __syncthreads();

    {
        float* ga = g_A + (size_t)i * 12 * LL;
        for (int x = tid * 4; x < 12 * LL; x += 1024)
            *(float4*)(ga + x) = *(const float4*)&sA[x];
    }

    if (tid < 240) {
        int h = tid / 20, o = (tid % 20) * 2;
        const float* s0;
        if (o < 16) s0 = g_vT + (h*16+o)*LL;
        else        s0 = g_vppT + (h*24+o-16)*LL;
        const float* s1p = s0 + LL;
        const float* ap = sA + h * LL;
        float a0 = 0.f, a1 = 0.f;
        for (int j = 0; j < LL; j += 8) {
            float4 v0a = *(const float4*)(s0 + j),  v0b = *(const float4*)(s0 + j + 4);
            float4 v1a = *(const float4*)(s1p + j), v1b = *(const float4*)(s1p + j + 4);
            float4 aa  = *(const float4*)(ap + j),  ab  = *(const float4*)(ap + j + 4);
            a0 = fmaf(aa.x,v0a.x,fmaf(aa.y,v0a.y,fmaf(aa.z,v0a.z,fmaf(aa.w,v0a.w,a0))));
            a0 = fmaf(ab.x,v0b.x,fmaf(ab.y,v0b.y,fmaf(ab.z,v0b.z,fmaf(ab.w,v0b.w,a0))));
            a1 = fmaf(aa.x,v1a.x,fmaf(aa.y,v1a.y,fmaf(aa.z,v1a.z,fmaf(aa.w,v1a.w,a1))));
            a1 = fmaf(ab.x,v1b.x,fmaf(ab.y,v1b.y,fmaf(ab.z,v1b.z,fmaf(ab.w,v1b.w,a1))));
        }
        float* orow = g_shid + (size_t)i * SH + h * 304;
        if (o < 16) { orow[256+o] = a0; orow[257+o] = a1; }
        else        { sOVP[h*24 + o-16] = a0; sOVP[h*24 + o-15] = a1; }
    }
    __syncthreads();

    if (tid < 96) {
        int h = tid >> 3, vv = tid & 7;
        float gx = sOVP[h*24 + vv*3 + 0] - st3[0];
        float gy = sOVP[h*24 + vv*3 + 1] - st3[1];
        float gz = sOVP[h*24 + vv*3 + 2] - st3[2];
        float lx = sR[0]*gx + sR[3]*gy + sR[6]*gz;
        float ly = sR[1]*gx + sR[4]*gy + sR[7]*gz;
        float lz = sR[2]*gx + sR[5]*gy + sR[8]*gz;
        float* orow = g_shid + (size_t)i * SH + h * 304;
        orow[272 + vv*3 + 0] = lx;
        orow[272 + vv*3 + 1] = ly;
        orow[272 + vv*3 + 2] = lz;
        orow[296 + vv] = sqrtf(lx*lx + ly*ly + lz*lz);
    }
}

// op = a^T @ z per query row, packed f32x2; one CTA per i
__global__ __launch_bounds__(256) void op_gemm(const float* __restrict__ z)
{
    __shared__ float sA[12 * LL];   // 24 KB
    int i = blockIdx.x, tid = threadIdx.x;
    const float* ga = g_A + (size_t)i * 12 * LL;
    for (int x = tid * 4; x < 12 * LL; x += 1024)
        *(float4*)&sA[x] = *(const float4*)(ga + x);
    __syncthreads();

    int h0 = (tid >> 6) * 3;
    int cc = (tid & 63) << 2;
    const float* zp = z + (size_t)i * LL * CZ + cc;
    const float* a0p = sA + (h0+0) * LL;
    const float* a1p = sA + (h0+1) * LL;
    const float* a2p = sA + (h0+2) * LL;
    u64 acc[3][2] = {};
    for (int j = 0; j < LL; j += 4) {
        ulonglong2 zv[4];
        #pragma unroll
        for (int u = 0; u < 4; u++)
            zv[u] = *(const ulonglong2*)(zp + (size_t)(j+u) * CZ);
        float4 a0 = *(const float4*)(a0p + j);
        float4 a1 = *(const float4*)(a1p + j);
        float4 a2 = *(const float4*)(a2p + j);
        float a0v[4] = {a0.x,a0.y,a0.z,a0.w};
        float a1v[4] = {a1.x,a1.y,a1.z,a1.w};
        float a2v[4] = {a2.x,a2.y,a2.z,a2.w};
        #pragma unroll
        for (int u = 0; u < 4; u++) {
            u64 d0 = dup2(a0v[u]), d1 = dup2(a1v[u]), d2 = dup2(a2v[u]);
            ffma2(acc[0][0], zv[u].x, d0); ffma2(acc[0][1], zv[u].y, d0);
            ffma2(acc[1][0], zv[u].x, d1); ffma2(acc[1][1], zv[u].y, d1);
            ffma2(acc[2][0], zv[u].x, d2); ffma2(acc[2][1], zv[u].y, d2);
        }
    }
    float* orow = g_shid + (size_t)i * SH;
    #pragma unroll
    for (int hh = 0; hh < 3; hh++) {
        ulonglong2 st; st.x = acc[hh][0]; st.y = acc[hh][1];
        *(ulonglong2*)(orow + (h0+hh)*304 + cc) = st;
    }
}

extern "C" void kernel_launch(void* const* d_in, const int* in_sizes, int n_in,
                              void* d_out, int out_size)
{
    const float* s    = (const float*)d_in[0];
    const float* z    = (const float*)d_in[1];
    const float* quat = (const float*)d_in[2];
    const float* trsl = (const float*)d_in[3];
    const float* Wq   = (const float*)d_in[4];
    const float* Wk   = (const float*)d_in[5];
    const float* Wv   = (const float*)d_in[6];
    const float* Wqp  = (const float*)d_in[7];
    const float* Wkp  = (const float*)d_in[8];
    const float* Wvp  = (const float*)d_in[9];
    const float* Wb   = (const float*)d_in[10];
    const float* Ws   = (const float*)d_in[11];
    const float* bs   = (const float*)d_in[12];
    const float* scale= (const float*)d_in[13];
    const float* g1   = (const float*)d_in[14];
    const float* b1   = (const float*)d_in[15];
    const float* Wm1  = (const float*)d_in[16];
    const float* bm1  = (const float*)d_in[17];
    const float* Wm2  = (const float*)d_in[18];
    const float* bm2  = (const float*)d_in[19];
    const float* Wm3  = (const float*)d_in[20];
    const float* bm3  = (const float*)d_in[21];
    const float* g2   = (const float*)d_in[22];
    const float* b2   = (const float*)d_in[23];
    float* out = (float*)d_out;

    void *pWcat, *pProj, *pShid, *pParts, *pS1, *pH1, *pH2;
    cudaGetSymbolAddress(&pWcat,  g_Wcat);
    cudaGetSymbolAddress(&pProj,  g_proj);
    cudaGetSymbolAddress(&pShid,  g_shid);
    cudaGetSymbolAddress(&pParts, g_parts);
    cudaGetSymbolAddress(&pS1,    g_s1);
    cudaGetSymbolAddress(&pH1,    g_h1);
    cudaGetSymbolAddress(&pH2,    g_h2);
    float* Wcat = (float*)pWcat;  float* proj = (float*)pProj;
    float* shid = (float*)pShid;  float* parts = (float*)pParts;
    float* s1 = (float*)pS1;      float* h1 = (float*)pH1;
    float* h2 = (float*)pH2;

    const int TOT = LL * CS;
    const int PTOT = LL * PW;

    pack_prep<<<(CS*PW + 255)/256, 256>>>(Wq, Wk, Wv, Wqp, Wkp, Wvp, quat, trsl, scale);
    bias_gemm<<<(LL*LL)/256, 256>>>(z, Wb);
    // projections: s[512,384] @ Wcat[384,1152], split-K=2
    gemm128<<<dim3(PW/64, LL/128, 2), 256>>>(s, Wcat, parts, CS, PW, PW, CS/2, CS, PTOT);
    combine<<<(PTOT+255)/256, 256>>>(parts, 2, PTOT, (const float*)0, proj, PTOT, PW, 0);
    transform<<<LL, 384>>>();
    attn<<<LL, 256>>>();
    op_gemm<<<LL, 256>>>(z);
    // shid[512,3648] @ Ws[3648,384], split-K=6
    gemm128<<<dim3(CS/64, LL/128, 6), 256>>>(shid, Ws, parts, SH, CS, CS, SH/6, SH, TOT);
    ln_combine<<<LL, 128>>>(parts, 6, TOT, bs, s, g1, b1, s1);
    // MLP, split-K=6 each
    gemm128<<<dim3(CS/64, LL/128, 6), 256>>>(s1, Wm1, parts, CS, CS, CS, CS/6, CS, TOT);
    combine<<<(TOT+255)/256, 256>>>(parts, 6, TOT, bm1, h1, TOT, CS, 1);
    gemm128<<<dim3(CS/64, LL/128, 6), 256>>>(h1, Wm2, parts, CS, CS, CS, CS/6, CS, TOT);
    combine<<<(TOT+255)/256, 256>>>(parts, 6, TOT, bm2, h2, TOT, CS, 1);
    gemm128<<<dim3(CS/64, LL/128, 6), 256>>>(h2, Wm3, parts, CS, CS, CS, CS/6, CS, TOT);
    ln_combine<<<LL, 128>>>(parts, 6, TOT, bm3, s1, g2, b2, out);
}